// round 9
// baseline (speedup 1.0000x reference)
#include <cuda_runtime.h>
#include <math.h>

#define NUM_NODES   2000000
#define NUM_MOVABLE 1500000
#define NUM_FILLER  400000
#define NUM_NETS    1500000
#define NUM_PINS    6000000
#define NB          512
#define NBP         513          // padded dim for diff map
#define BIN_W       1.953125f
#define UNIT_CAP    1.5f
#define EPSF        1e-6f

// ---------------- scratch (static device globals; no allocations) -----------
// All bin grids laid out [y*dim + x].
__device__ float2 g_pin_xy[NUM_PINS];   // interleaved (x,y) per physical pin
__device__ float2 g_D[NBP * NBP];       // diff map [y*NBP + x], padded
__device__ float2 g_Sf[NB * NB];        // scan_x result [y*NB + x]
__device__ float  g_ratio[NB * NB];     // ratio map [y*NB + x]
__device__ float  g_binarea[NB * NB];   // per-bin movable area [y*NB + x]
__device__ double g_sum_area;
__device__ double g_sum_route;
__device__ double g_sum_filler;

__device__ __forceinline__ int bin_of(float v) {
    int b = (int)floorf(v / BIN_W);
    return min(max(b, 0), NB - 1);
}

// one L2 atomic op for the adjacent (dh, dv) pair
__device__ __forceinline__ void red2(float2* addr, float a, float b) {
    asm volatile("red.global.add.v2.f32 [%0], {%1, %2};"
                 :: "l"(addr), "f"(a), "f"(b) : "memory");
}

// ---------------- kernel 1: pin transpose + zero scratch --------------------
#define PIN_GROUPS (NUM_PINS / 4)          // 1.5M
__global__ void k_prep(const float4* __restrict__ px4,
                       const float4* __restrict__ py4) {
    int g = blockIdx.x * blockDim.x + threadIdx.x;
    if (g < PIN_GROUPS) {
        float4 x = px4[g];
        float4 y = py4[g];
        float4* out = (float4*)g_pin_xy;
        out[g * 2]     = make_float4(x.x, y.x, x.y, y.y);
        out[g * 2 + 1] = make_float4(x.z, y.z, x.w, y.w);
    }
    if (g < NBP * NBP) g_D[g] = make_float2(0.0f, 0.0f);
    if (g < NB * NB)   g_binarea[g] = 0.0f;
    if (g == 0) {
        g_sum_area   = 0.0;
        g_sum_route  = 0.0;
        g_sum_filler = 0.0;
    }
}

// ---------------- kernel 2: fused nets-scatter + node sums ------------------
#define NET_PER_THREAD 2
#define NET_THREADS    (NUM_NETS / NET_PER_THREAD)          // 750000
#define NET_BLOCKS     ((NET_THREADS + 255) / 256)          // 2930
#define AREA_GROUPS    (NUM_NODES / 4)                      // 500000
#define AREA_BLOCKS    ((AREA_GROUPS + 255) / 256)          // 1954

__device__ __forceinline__ void net_scatter(int4 fp) {
    float2 p0 = __ldg(&g_pin_xy[fp.x]);
    float2 p1 = __ldg(&g_pin_xy[fp.y]);
    float2 p2 = __ldg(&g_pin_xy[fp.z]);
    float2 p3 = __ldg(&g_pin_xy[fp.w]);

    float xl = fminf(fminf(p0.x, p1.x), fminf(p2.x, p3.x));
    float xh = fmaxf(fmaxf(p0.x, p1.x), fmaxf(p2.x, p3.x));
    float yl = fminf(fminf(p0.y, p1.y), fminf(p2.y, p3.y));
    float yh = fmaxf(fmaxf(p0.y, p1.y), fmaxf(p2.y, p3.y));

    float bw = xh - xl;
    float bh = yh - yl;
    float barea = fmaxf(bw * bh, EPSF);
    float dh = bw / barea;
    float dv = bh / barea;

    int blx = bin_of(xl);
    int bhx = bin_of(xh) + 1;   // up to 512: lands in padding (never read)
    int bly = bin_of(yl);
    int bhy = bin_of(yh) + 1;

    red2(&g_D[bly * NBP + blx],  dh,  dv);
    red2(&g_D[bly * NBP + bhx], -dh, -dv);
    red2(&g_D[bhy * NBP + blx], -dh, -dv);
    red2(&g_D[bhy * NBP + bhx],  dh,  dv);
}

__global__ void k_fused(const int* __restrict__ flat_netpin,
                        const float4* __restrict__ pos4,
                        const float4* __restrict__ posy4,
                        const float4* __restrict__ nsx4,
                        const float4* __restrict__ nsy4) {
    if (blockIdx.x < NET_BLOCKS) {
        int gid = blockIdx.x * blockDim.x + threadIdx.x;
        int n0 = gid * NET_PER_THREAD;
        if (n0 >= NUM_NETS) return;
        const int4* fp4 = (const int4*)flat_netpin;
        int4 a = fp4[n0];
        int4 b = fp4[n0 + 1];
        net_scatter(a);
        net_scatter(b);
        return;
    }

    // ---- area part ----
    int g = (blockIdx.x - NET_BLOCKS) * blockDim.x + threadIdx.x;
    double la = 0.0, lf = 0.0;
    if (g < AREA_GROUPS) {
        int i0 = g * 4;
        float4 sx = nsx4[g];
        float4 sy = nsy4[g];
        if (i0 < NUM_MOVABLE) {
            float4 px = pos4[g];
            float4 py = posy4[g];
            float a0 = sx.x * sy.x, a1 = sx.y * sy.y;
            float a2 = sx.z * sy.z, a3 = sx.w * sy.w;
            int b0 = bin_of(py.x + 0.5f * sy.x) * NB + bin_of(px.x + 0.5f * sx.x);
            int b1 = bin_of(py.y + 0.5f * sy.y) * NB + bin_of(px.y + 0.5f * sx.y);
            int b2 = bin_of(py.z + 0.5f * sy.z) * NB + bin_of(px.z + 0.5f * sx.z);
            int b3 = bin_of(py.w + 0.5f * sy.w) * NB + bin_of(px.w + 0.5f * sx.w);
            atomicAdd(&g_binarea[b0], a0);
            atomicAdd(&g_binarea[b1], a1);
            atomicAdd(&g_binarea[b2], a2);
            atomicAdd(&g_binarea[b3], a3);
            la = (double)a0 + (double)a1 + (double)a2 + (double)a3;
        } else if (i0 >= NUM_NODES - NUM_FILLER) {
            lf = (double)(sx.x * sy.x) + (double)(sx.y * sy.y)
               + (double)(sx.z * sy.z) + (double)(sx.w * sy.w);
        }
    }
    for (int off = 16; off > 0; off >>= 1) {
        la += __shfl_down_sync(0xFFFFFFFFu, la, off);
        lf += __shfl_down_sync(0xFFFFFFFFu, lf, off);
    }
    if ((threadIdx.x & 31) == 0) {
        if (la != 0.0) atomicAdd(&g_sum_area,   la);
        if (lf != 0.0) atomicAdd(&g_sum_filler, lf);
    }
}

// ---------------- block-wide inclusive scan (512 threads, double2) ----------
__device__ __forceinline__ double2 block_scan_512(double2 v) {
    __shared__ double2 partials[16];
    int lane = threadIdx.x & 31;
    int warp = threadIdx.x >> 5;
    #pragma unroll
    for (int off = 1; off < 32; off <<= 1) {
        double ax = __shfl_up_sync(0xFFFFFFFFu, v.x, off);
        double ay = __shfl_up_sync(0xFFFFFFFFu, v.y, off);
        if (lane >= off) { v.x += ax; v.y += ay; }
    }
    if (lane == 31) partials[warp] = v;
    __syncthreads();
    if (warp == 0 && lane < 16) {
        double2 p = partials[lane];
        #pragma unroll
        for (int off = 1; off < 16; off <<= 1) {
            double ax = __shfl_up_sync(0x0000FFFFu, p.x, off);
            double ay = __shfl_up_sync(0x0000FFFFu, p.y, off);
            if (lane >= off) { p.x += ax; p.y += ay; }
        }
        partials[lane] = p;
    }
    __syncthreads();
    if (warp > 0) {
        double2 p = partials[warp - 1];
        v.x += p.x; v.y += p.y;
    }
    return v;
}

// ---------------- kernel 3: inclusive scan along x (fully coalesced) --------
__global__ void k_scan_x() {
    int y = blockIdx.x;
    int x = threadIdx.x;
    float2 d = g_D[y * NBP + x];
    double2 v = make_double2((double)d.x, (double)d.y);
    v = block_scan_512(v);
    g_Sf[y * NB + x] = make_float2((float)v.x, (float)v.y);
}

// ---------------- kernel 4: tiled scan along y + ratio + dot (coalesced) ----
// Grid 16 blocks, block (32, 16). Block owns 32 x-columns; thread (tx, ty)
// owns y in [ty*32, ty*32+32) of column x. Two passes: chunk sums -> offset
// scan over 16 partials -> rescan with offset. All global accesses coalesced.
__global__ void k_scan_y_ratio() {
    __shared__ float2 part[16][33];
    __shared__ double s_route[16];
    int tx = threadIdx.x;          // 0..31 column within block
    int ty = threadIdx.y;          // 0..15 y-chunk
    int x  = blockIdx.x * 32 + tx;
    int y0 = ty * 32;

    // pass 1: chunk sums
    float2 acc = make_float2(0.0f, 0.0f);
    #pragma unroll 8
    for (int j = 0; j < 32; j++) {
        float2 v = g_Sf[(y0 + j) * NB + x];
        acc.x += v.x; acc.y += v.y;
    }
    part[ty][tx] = acc;
    __syncthreads();

    // exclusive offset over the 16 chunk partials of this column
    float2 off = make_float2(0.0f, 0.0f);
    for (int k = 0; k < 16; k++) {
        if (k < ty) {
            float2 p = part[k][tx];
            off.x += p.x; off.y += p.y;
        }
    }

    // pass 2: rescan with offset, emit ratio, accumulate dot
    float runx = off.x, runy = off.y;
    double lr = 0.0;
    #pragma unroll 8
    for (int j = 0; j < 32; j++) {
        int idx = (y0 + j) * NB + x;
        float2 v = g_Sf[idx];
        runx += v.x; runy += v.y;
        float uh = runx / UNIT_CAP;
        float uv = runy / UNIT_CAP;
        float r = fminf(fmaxf(fmaxf(uh, uv), 0.5f), 2.0f);
        g_ratio[idx] = r;
        lr += (double)(r * g_binarea[idx]);
    }

    // block-reduce dot -> sum_route
    for (int o = 16; o > 0; o >>= 1)
        lr += __shfl_down_sync(0xFFFFFFFFu, lr, o);
    if (tx == 0) s_route[ty] = lr;
    __syncthreads();
    if (ty == 0 && tx == 0) {
        double t = 0.0;
        for (int k = 0; k < 16; k++) t += s_route[k];
        atomicAdd(&g_sum_route, t);
    }
}

// ---------------- kernel 5: outputs (float4, inline scalars) ----------------
__global__ void k_output(const float4* __restrict__ pos4,
                         const float4* __restrict__ posy4,
                         const float4* __restrict__ nsx4,
                         const float4* __restrict__ nsy4,
                         float4* __restrict__ out) {
    int g = blockIdx.x * blockDim.x + threadIdx.x;
    if (g >= NUM_NODES / 4) return;
    int i0 = g * 4;

    // scalars from global sums (uniform broadcast loads)
    float sum_area   = (float)g_sum_area;
    float sum_route  = (float)g_sum_route;
    float sum_filler = (float)g_sum_filler;
    float max_total  = sum_area + sum_filler;
    float scale  = fminf(1.0f, max_total / fmaxf(sum_route, EPSF));
    float fscale = sqrtf(fmaxf(max_total - sum_route * scale, 0.0f) /
                         fmaxf(sum_filler, EPSF));

    float4 x  = pos4[g];
    float4 y  = posy4[g];
    float4 sx = nsx4[g];
    float4 sy = nsy4[g];

    float4 xo = x, yo = y, sxo = sx, syo = sy;

    if (i0 < NUM_MOVABLE) {
        {
            float r = g_ratio[bin_of(y.x + 0.5f * sy.x) * NB + bin_of(x.x + 0.5f * sx.x)];
            float sr = sqrtf(r * scale);
            float nx = sx.x * sr, ny = sy.x * sr;
            xo.x = x.x + 0.5f * (sx.x - nx); yo.x = y.x + 0.5f * (sy.x - ny);
            sxo.x = nx; syo.x = ny;
        }
        {
            float r = g_ratio[bin_of(y.y + 0.5f * sy.y) * NB + bin_of(x.y + 0.5f * sx.y)];
            float sr = sqrtf(r * scale);
            float nx = sx.y * sr, ny = sy.y * sr;
            xo.y = x.y + 0.5f * (sx.y - nx); yo.y = y.y + 0.5f * (sy.y - ny);
            sxo.y = nx; syo.y = ny;
        }
        {
            float r = g_ratio[bin_of(y.z + 0.5f * sy.z) * NB + bin_of(x.z + 0.5f * sx.z)];
            float sr = sqrtf(r * scale);
            float nx = sx.z * sr, ny = sy.z * sr;
            xo.z = x.z + 0.5f * (sx.z - nx); yo.z = y.z + 0.5f * (sy.z - ny);
            sxo.z = nx; syo.z = ny;
        }
        {
            float r = g_ratio[bin_of(y.w + 0.5f * sy.w) * NB + bin_of(x.w + 0.5f * sx.w)];
            float sr = sqrtf(r * scale);
            float nx = sx.w * sr, ny = sy.w * sr;
            xo.w = x.w + 0.5f * (sx.w - nx); yo.w = y.w + 0.5f * (sy.w - ny);
            sxo.w = nx; syo.w = ny;
        }
    } else if (i0 >= NUM_NODES - NUM_FILLER) {
        sxo.x = sx.x * fscale; sxo.y = sx.y * fscale;
        sxo.z = sx.z * fscale; sxo.w = sx.w * fscale;
        syo.x = sy.x * fscale; syo.y = sy.y * fscale;
        syo.z = sy.z * fscale; syo.w = sy.w * fscale;
    }

    const int Q = NUM_NODES / 4;
    out[g]         = xo;
    out[Q + g]     = yo;
    out[2 * Q + g] = sxo;
    out[3 * Q + g] = syo;
}

// ---------------- launch -----------------------------------------------------
extern "C" void kernel_launch(void* const* d_in, const int* in_sizes, int n_in,
                              void* d_out, int out_size) {
    const float* pos         = (const float*)d_in[0];
    const float* pin_pos     = (const float*)d_in[1];
    const float* node_size_x = (const float*)d_in[2];
    const float* node_size_y = (const float*)d_in[3];
    const int*   flat_netpin = (const int*)d_in[4];
    float* out = (float*)d_out;

    const float4* pos4  = (const float4*)pos;
    const float4* posy4 = (const float4*)(pos + NUM_NODES);
    const float4* nsx4  = (const float4*)node_size_x;
    const float4* nsy4  = (const float4*)node_size_y;
    const float4* px4   = (const float4*)pin_pos;
    const float4* py4   = (const float4*)(pin_pos + NUM_PINS);

    const int Q = NUM_NODES / 4;

    k_prep<<<(PIN_GROUPS + 255) / 256, 256>>>(px4, py4);
    k_fused<<<NET_BLOCKS + AREA_BLOCKS, 256>>>(flat_netpin,
                                               pos4, posy4, nsx4, nsy4);
    k_scan_x<<<NB, NB>>>();
    k_scan_y_ratio<<<16, dim3(32, 16)>>>();
    k_output<<<(Q + 255) / 256, 256>>>(pos4, posy4, nsx4, nsy4, (float4*)out);
}

// round 10
// speedup vs baseline: 1.0909x; 1.0909x over previous
#include <cuda_runtime.h>
#include <math.h>

#define NUM_NODES   2000000
#define NUM_MOVABLE 1500000
#define NUM_FILLER  400000
#define NUM_NETS    1500000
#define NUM_PINS    6000000
#define NB          512
#define NBP         513          // padded dim for diff map
#define BIN_W       1.953125f
#define UNIT_CAP    1.5f
#define EPSF        1e-6f

// ---------------- scratch (static device globals; no allocations) -----------
__device__ float2 g_pin_xy[NUM_PINS];   // interleaved (x,y) per physical pin
__device__ float2 g_D[NBP * NBP];       // diff map [y*NBP + x], padded
__device__ float2 g_Sf[NB * NB];        // scan_x result [y*NB + x] (float2)
__device__ float  g_ratio[NB * NB];     // ratio map [x*NB + y]
__device__ float  g_binarea[NB * NB];   // per-bin movable area [x*NB + y]
__device__ double g_sum_area;
__device__ double g_sum_route;
__device__ double g_sum_filler;

__device__ __forceinline__ int bin_of(float v) {
    int b = (int)floorf(v / BIN_W);
    return min(max(b, 0), NB - 1);
}

// one L2 atomic op for the adjacent (dh, dv) pair
__device__ __forceinline__ void red2(float2* addr, float a, float b) {
    asm volatile("red.global.add.v2.f32 [%0], {%1, %2};"
                 :: "l"(addr), "f"(a), "f"(b) : "memory");
}

// ---------------- kernel 1: pin transpose + zero scratch --------------------
#define PIN_GROUPS (NUM_PINS / 4)          // 1.5M
__global__ void k_prep(const float4* __restrict__ px4,
                       const float4* __restrict__ py4) {
    int g = blockIdx.x * blockDim.x + threadIdx.x;
    if (g < PIN_GROUPS) {
        float4 x = px4[g];
        float4 y = py4[g];
        float4* out = (float4*)g_pin_xy;
        out[g * 2]     = make_float4(x.x, y.x, x.y, y.y);
        out[g * 2 + 1] = make_float4(x.z, y.z, x.w, y.w);
    }
    if (g < NBP * NBP) g_D[g] = make_float2(0.0f, 0.0f);
    if (g < NB * NB)   g_binarea[g] = 0.0f;
    if (g == 0) {
        g_sum_area   = 0.0;
        g_sum_route  = 0.0;
        g_sum_filler = 0.0;
    }
}

// ---------------- kernel 2: fused nets-scatter + node sums ------------------
#define NET_PER_THREAD 2
#define NET_THREADS    (NUM_NETS / NET_PER_THREAD)          // 750000
#define NET_BLOCKS     ((NET_THREADS + 255) / 256)          // 2930
#define AREA_GROUPS    (NUM_NODES / 4)                      // 500000
#define AREA_BLOCKS    ((AREA_GROUPS + 255) / 256)          // 1954

__device__ __forceinline__ void net_scatter(int4 fp) {
    float2 p0 = __ldg(&g_pin_xy[fp.x]);
    float2 p1 = __ldg(&g_pin_xy[fp.y]);
    float2 p2 = __ldg(&g_pin_xy[fp.z]);
    float2 p3 = __ldg(&g_pin_xy[fp.w]);

    float xl = fminf(fminf(p0.x, p1.x), fminf(p2.x, p3.x));
    float xh = fmaxf(fmaxf(p0.x, p1.x), fmaxf(p2.x, p3.x));
    float yl = fminf(fminf(p0.y, p1.y), fminf(p2.y, p3.y));
    float yh = fmaxf(fmaxf(p0.y, p1.y), fmaxf(p2.y, p3.y));

    float bw = xh - xl;
    float bh = yh - yl;
    float barea = fmaxf(bw * bh, EPSF);
    float dh = bw / barea;
    float dv = bh / barea;

    int blx = bin_of(xl);
    int bhx = bin_of(xh) + 1;   // up to 512: lands in padding (never read)
    int bly = bin_of(yl);
    int bhy = bin_of(yh) + 1;

    red2(&g_D[bly * NBP + blx],  dh,  dv);
    red2(&g_D[bly * NBP + bhx], -dh, -dv);
    red2(&g_D[bhy * NBP + blx], -dh, -dv);
    red2(&g_D[bhy * NBP + bhx],  dh,  dv);
}

__global__ void k_fused(const int* __restrict__ flat_netpin,
                        const float4* __restrict__ pos4,
                        const float4* __restrict__ posy4,
                        const float4* __restrict__ nsx4,
                        const float4* __restrict__ nsy4) {
    if (blockIdx.x < NET_BLOCKS) {
        int gid = blockIdx.x * blockDim.x + threadIdx.x;
        int n0 = gid * NET_PER_THREAD;
        if (n0 >= NUM_NETS) return;
        const int4* fp4 = (const int4*)flat_netpin;
        int4 a = fp4[n0];
        int4 b = fp4[n0 + 1];
        net_scatter(a);
        net_scatter(b);
        return;
    }

    // ---- area part ----
    int g = (blockIdx.x - NET_BLOCKS) * blockDim.x + threadIdx.x;
    double la = 0.0, lf = 0.0;
    if (g < AREA_GROUPS) {
        int i0 = g * 4;
        float4 sx = nsx4[g];
        float4 sy = nsy4[g];
        if (i0 < NUM_MOVABLE) {
            float4 px = pos4[g];
            float4 py = posy4[g];
            float a0 = sx.x * sy.x, a1 = sx.y * sy.y;
            float a2 = sx.z * sy.z, a3 = sx.w * sy.w;
            int b0 = bin_of(px.x + 0.5f * sx.x) * NB + bin_of(py.x + 0.5f * sy.x);
            int b1 = bin_of(px.y + 0.5f * sx.y) * NB + bin_of(py.y + 0.5f * sy.y);
            int b2 = bin_of(px.z + 0.5f * sx.z) * NB + bin_of(py.z + 0.5f * sy.z);
            int b3 = bin_of(px.w + 0.5f * sx.w) * NB + bin_of(py.w + 0.5f * sy.w);
            atomicAdd(&g_binarea[b0], a0);
            atomicAdd(&g_binarea[b1], a1);
            atomicAdd(&g_binarea[b2], a2);
            atomicAdd(&g_binarea[b3], a3);
            la = (double)a0 + (double)a1 + (double)a2 + (double)a3;
        } else if (i0 >= NUM_NODES - NUM_FILLER) {
            lf = (double)(sx.x * sy.x) + (double)(sx.y * sy.y)
               + (double)(sx.z * sy.z) + (double)(sx.w * sy.w);
        }
    }
    for (int off = 16; off > 0; off >>= 1) {
        la += __shfl_down_sync(0xFFFFFFFFu, la, off);
        lf += __shfl_down_sync(0xFFFFFFFFu, lf, off);
    }
    if ((threadIdx.x & 31) == 0) {
        if (la != 0.0) atomicAdd(&g_sum_area,   la);
        if (lf != 0.0) atomicAdd(&g_sum_filler, lf);
    }
}

// ---------------- block-wide inclusive scan (512 threads, double2) ----------
__device__ __forceinline__ double2 block_scan_512(double2 v) {
    __shared__ double2 partials[16];
    int lane = threadIdx.x & 31;
    int warp = threadIdx.x >> 5;
    #pragma unroll
    for (int off = 1; off < 32; off <<= 1) {
        double ax = __shfl_up_sync(0xFFFFFFFFu, v.x, off);
        double ay = __shfl_up_sync(0xFFFFFFFFu, v.y, off);
        if (lane >= off) { v.x += ax; v.y += ay; }
    }
    if (lane == 31) partials[warp] = v;
    __syncthreads();
    if (warp == 0 && lane < 16) {
        double2 p = partials[lane];
        #pragma unroll
        for (int off = 1; off < 16; off <<= 1) {
            double ax = __shfl_up_sync(0x0000FFFFu, p.x, off);
            double ay = __shfl_up_sync(0x0000FFFFu, p.y, off);
            if (lane >= off) { p.x += ax; p.y += ay; }
        }
        partials[lane] = p;
    }
    __syncthreads();
    if (warp > 0) {
        double2 p = partials[warp - 1];
        v.x += p.x; v.y += p.y;
    }
    return v;
}

// ---------------- kernel 3: inclusive scan along x (fully coalesced) --------
__global__ void k_scan_x() {
    int y = blockIdx.x;
    int x = threadIdx.x;
    float2 d = g_D[y * NBP + x];
    double2 v = make_double2((double)d.x, (double)d.y);
    v = block_scan_512(v);
    g_Sf[y * NB + x] = make_float2((float)v.x, (float)v.y);
}

// ---------------- kernel 4: scan along y + ratio + dot ----------------------
// Block = x column (512 blocks), thread = y. g_Sf read strided (8B/lane);
// ratio write and binarea read coalesced via [x*NB + y] layout.
__global__ void k_scan_y_ratio() {
    __shared__ double s_route[16];
    int x = blockIdx.x;
    int y = threadIdx.x;
    int lane = threadIdx.x & 31;
    int warp = threadIdx.x >> 5;

    float2 d = g_Sf[y * NB + x];
    double2 v = make_double2((double)d.x, (double)d.y);
    v = block_scan_512(v);
    float uh = (float)v.x / UNIT_CAP;
    float uv = (float)v.y / UNIT_CAP;
    float r = fminf(fmaxf(fmaxf(uh, uv), 0.5f), 2.0f);
    int idx = x * NB + y;
    g_ratio[idx] = r;

    // fused dot(ratio, binarea) for sum_route
    double lr = (double)(r * g_binarea[idx]);
    for (int off = 16; off > 0; off >>= 1)
        lr += __shfl_down_sync(0xFFFFFFFFu, lr, off);
    if (lane == 0) s_route[warp] = lr;
    __syncthreads();
    if (warp == 0) {
        double t = (lane < 16) ? s_route[lane] : 0.0;
        for (int off = 8; off > 0; off >>= 1)
            t += __shfl_down_sync(0xFFFFFFFFu, t, off);
        if (lane == 0 && t != 0.0) atomicAdd(&g_sum_route, t);
    }
}

// ---------------- kernel 5: outputs (float4, inline scalars) ----------------
__global__ void k_output(const float4* __restrict__ pos4,
                         const float4* __restrict__ posy4,
                         const float4* __restrict__ nsx4,
                         const float4* __restrict__ nsy4,
                         float4* __restrict__ out) {
    int g = blockIdx.x * blockDim.x + threadIdx.x;
    if (g >= NUM_NODES / 4) return;
    int i0 = g * 4;

    // scalars from global sums (uniform broadcast loads)
    float sum_area   = (float)g_sum_area;
    float sum_route  = (float)g_sum_route;
    float sum_filler = (float)g_sum_filler;
    float max_total  = sum_area + sum_filler;
    float scale  = fminf(1.0f, max_total / fmaxf(sum_route, EPSF));
    float fscale = sqrtf(fmaxf(max_total - sum_route * scale, 0.0f) /
                         fmaxf(sum_filler, EPSF));

    float4 x  = pos4[g];
    float4 y  = posy4[g];
    float4 sx = nsx4[g];
    float4 sy = nsy4[g];

    float4 xo = x, yo = y, sxo = sx, syo = sy;

    if (i0 < NUM_MOVABLE) {
        {
            float r = g_ratio[bin_of(x.x + 0.5f * sx.x) * NB + bin_of(y.x + 0.5f * sy.x)];
            float sr = sqrtf(r * scale);
            float nx = sx.x * sr, ny = sy.x * sr;
            xo.x = x.x + 0.5f * (sx.x - nx); yo.x = y.x + 0.5f * (sy.x - ny);
            sxo.x = nx; syo.x = ny;
        }
        {
            float r = g_ratio[bin_of(x.y + 0.5f * sx.y) * NB + bin_of(y.y + 0.5f * sy.y)];
            float sr = sqrtf(r * scale);
            float nx = sx.y * sr, ny = sy.y * sr;
            xo.y = x.y + 0.5f * (sx.y - nx); yo.y = y.y + 0.5f * (sy.y - ny);
            sxo.y = nx; syo.y = ny;
        }
        {
            float r = g_ratio[bin_of(x.z + 0.5f * sx.z) * NB + bin_of(y.z + 0.5f * sy.z)];
            float sr = sqrtf(r * scale);
            float nx = sx.z * sr, ny = sy.z * sr;
            xo.z = x.z + 0.5f * (sx.z - nx); yo.z = y.z + 0.5f * (sy.z - ny);
            sxo.z = nx; syo.z = ny;
        }
        {
            float r = g_ratio[bin_of(x.w + 0.5f * sx.w) * NB + bin_of(y.w + 0.5f * sy.w)];
            float sr = sqrtf(r * scale);
            float nx = sx.w * sr, ny = sy.w * sr;
            xo.w = x.w + 0.5f * (sx.w - nx); yo.w = y.w + 0.5f * (sy.w - ny);
            sxo.w = nx; syo.w = ny;
        }
    } else if (i0 >= NUM_NODES - NUM_FILLER) {
        sxo.x = sx.x * fscale; sxo.y = sx.y * fscale;
        sxo.z = sx.z * fscale; sxo.w = sx.w * fscale;
        syo.x = sy.x * fscale; syo.y = sy.y * fscale;
        syo.z = sy.z * fscale; syo.w = sy.w * fscale;
    }

    const int Q = NUM_NODES / 4;
    out[g]         = xo;
    out[Q + g]     = yo;
    out[2 * Q + g] = sxo;
    out[3 * Q + g] = syo;
}

// ---------------- launch -----------------------------------------------------
extern "C" void kernel_launch(void* const* d_in, const int* in_sizes, int n_in,
                              void* d_out, int out_size) {
    const float* pos         = (const float*)d_in[0];
    const float* pin_pos     = (const float*)d_in[1];
    const float* node_size_x = (const float*)d_in[2];
    const float* node_size_y = (const float*)d_in[3];
    const int*   flat_netpin = (const int*)d_in[4];
    float* out = (float*)d_out;

    const float4* pos4  = (const float4*)pos;
    const float4* posy4 = (const float4*)(pos + NUM_NODES);
    const float4* nsx4  = (const float4*)node_size_x;
    const float4* nsy4  = (const float4*)node_size_y;
    const float4* px4   = (const float4*)pin_pos;
    const float4* py4   = (const float4*)(pin_pos + NUM_PINS);

    const int Q = NUM_NODES / 4;

    k_prep<<<(PIN_GROUPS + 255) / 256, 256>>>(px4, py4);
    k_fused<<<NET_BLOCKS + AREA_BLOCKS, 256>>>(flat_netpin,
                                               pos4, posy4, nsx4, nsy4);
    k_scan_x<<<NB, NB>>>();
    k_scan_y_ratio<<<NB, NB>>>();
    k_output<<<(Q + 255) / 256, 256>>>(pos4, posy4, nsx4, nsy4, (float4*)out);
}